// round 9
// baseline (speedup 1.0000x reference)
#include <cuda_runtime.h>
#include <cuda_bf16.h>

#define N_NODES 100000
#define N_EDGES 625000
#define GRID1_BLOCKS 592   // persistent grid; grid-stride self-balances

// Combined per-node projection table: g_AB[n] = {a0+bias0, a1+bias1, b0, b1}
__device__ float4 g_AB[N_NODES];

// 8 lanes per node-pair group, 4 groups per warp, 2 nodes per group -> 8 nodes/warp.
// Persistent warp-granular grid-stride over 12500 groups (exact division, no tail).
__global__ __launch_bounds__(256) void node_proj_kernel(
    const float4* __restrict__ x,    // [N_NODES * 32] float4
    const float4* __restrict__ W,    // [2 * 64] float4
    const float*  __restrict__ bias) // [2]
{
    int lane = threadIdx.x & 31;
    int g = lane >> 3;        // group 0..3
    int w = lane & 7;         // lane-in-group 0..7
    int warp_global = blockIdx.x * 8 + (threadIdx.x >> 5);
    const int n_warps = GRID1_BLOCKS * 8;
    const int N_GROUPS = N_NODES / 8;   // 12500 exactly

    float bi0 = __ldg(&bias[0]);
    float bi1 = __ldg(&bias[1]);

    for (int grp = warp_global; grp < N_GROUPS; grp += n_warps) {
        int nodeA = grp * 8 + g;
        int nodeB = nodeA + 4;

        const float4* xa = x + nodeA * 32;
        const float4* xb = x + nodeB * 32;
        float4 u0 = xa[w];
        float4 u1 = xa[w + 8];
        float4 u2 = xa[w + 16];
        float4 u3 = xa[w + 24];
        float4 v0 = xb[w];
        float4 v1 = xb[w + 8];
        float4 v2 = xb[w + 16];
        float4 v3 = xb[w + 24];

        float ua0 = 0.f, ua1 = 0.f, ub0 = 0.f, ub1 = 0.f;   // node A
        float va0 = 0.f, va1 = 0.f, vb0 = 0.f, vb1 = 0.f;   // node B

        #pragma unroll
        for (int j = 0; j < 4; j++) {
            float4 u = (j == 0) ? u0 : (j == 1) ? u1 : (j == 2) ? u2 : u3;
            float4 v = (j == 0) ? v0 : (j == 1) ? v1 : (j == 2) ? v2 : v3;
            int col = w + 8 * j;
            float4 wa0 = __ldg(&W[col]);        // class0 src half
            float4 wb0 = __ldg(&W[32 + col]);   // class0 dst half
            float4 wa1 = __ldg(&W[64 + col]);   // class1 src half
            float4 wb1 = __ldg(&W[96 + col]);   // class1 dst half

            ua0 += u.x * wa0.x + u.y * wa0.y + u.z * wa0.z + u.w * wa0.w;
            ub0 += u.x * wb0.x + u.y * wb0.y + u.z * wb0.z + u.w * wb0.w;
            ua1 += u.x * wa1.x + u.y * wa1.y + u.z * wa1.z + u.w * wa1.w;
            ub1 += u.x * wb1.x + u.y * wb1.y + u.z * wb1.z + u.w * wb1.w;

            va0 += v.x * wa0.x + v.y * wa0.y + v.z * wa0.z + v.w * wa0.w;
            vb0 += v.x * wb0.x + v.y * wb0.y + v.z * wb0.z + v.w * wb0.w;
            va1 += v.x * wa1.x + v.y * wa1.y + v.z * wa1.z + v.w * wa1.w;
            vb1 += v.x * wb1.x + v.y * wb1.y + v.z * wb1.z + v.w * wb1.w;
        }

        #pragma unroll
        for (int off = 4; off > 0; off >>= 1) {
            ua0 += __shfl_down_sync(0xFFFFFFFFu, ua0, off);
            ua1 += __shfl_down_sync(0xFFFFFFFFu, ua1, off);
            ub0 += __shfl_down_sync(0xFFFFFFFFu, ub0, off);
            ub1 += __shfl_down_sync(0xFFFFFFFFu, ub1, off);
            va0 += __shfl_down_sync(0xFFFFFFFFu, va0, off);
            va1 += __shfl_down_sync(0xFFFFFFFFu, va1, off);
            vb0 += __shfl_down_sync(0xFFFFFFFFu, vb0, off);
            vb1 += __shfl_down_sync(0xFFFFFFFFu, vb1, off);
        }

        if (w == 0) {
            g_AB[nodeA] = make_float4(ua0 + bi0, ua1 + bi1, ub0, ub1);
            g_AB[nodeB] = make_float4(va0 + bi0, va1 + bi1, vb0, vb1);
        }
    }

#if __CUDA_ARCH__ >= 900
    cudaTriggerProgrammaticLaunchCompletion();
#endif
}

// 1 edge per thread (fastest measured shape: max warps -> best L1tex wavefront
// interleave). PDL: index loads precede the grid-dependency-sync. Bias folded
// into A at projection time.
__global__ __launch_bounds__(256) void edge_score_kernel(
    const int* __restrict__ ei,      // [2 * N_EDGES] int32
    float2* __restrict__ out)        // [N_EDGES] float2
{
    int e = blockIdx.x * blockDim.x + threadIdx.x;

    int s = 0, d = 0;
    bool valid = (e < N_EDGES);
    if (valid) {
        s = __ldg(&ei[e]);
        d = __ldg(&ei[N_EDGES + e]);
    }

#if __CUDA_ARCH__ >= 900
    cudaGridDependencySynchronize();
#endif

    if (!valid) return;

    const float2* AB = (const float2*)g_AB;  // A at 2*n, B at 2*n+1
    float2 A = AB[2 * s];
    float2 B = AB[2 * d + 1];

    out[e] = make_float2(A.x + B.x, A.y + B.y);
}

extern "C" void kernel_launch(void* const* d_in, const int* in_sizes, int n_in,
                              void* d_out, int out_size)
{
    const float4* x   = (const float4*)d_in[0];   // [100000, 128] f32
    const int*    ei  = (const int*)d_in[1];      // [2, 625000] i32
    const float4* W   = (const float4*)d_in[2];   // [2, 256] f32
    const float*  b   = (const float*)d_in[3];    // [2] f32
    float2*       out = (float2*)d_out;

    // Kernel 1: persistent grid-stride over node groups.
    node_proj_kernel<<<GRID1_BLOCKS, 256>>>(x, W, b);

    // Kernel 2: per-edge gather with programmatic dependent launch.
    int grid2 = (N_EDGES + 255) / 256;

    cudaLaunchConfig_t cfg = {};
    cfg.gridDim  = dim3((unsigned)grid2, 1, 1);
    cfg.blockDim = dim3(256, 1, 1);
    cfg.dynamicSmemBytes = 0;
    cfg.stream = 0;
    cudaLaunchAttribute attrs[1];
    attrs[0].id = cudaLaunchAttributeProgrammaticStreamSerialization;
    attrs[0].val.programmaticStreamSerializationAllowed = 1;
    cfg.attrs = attrs;
    cfg.numAttrs = 1;

    cudaError_t err = cudaLaunchKernelEx(&cfg, edge_score_kernel, ei, out);
    if (err != cudaSuccess) {
        edge_score_kernel<<<grid2, 256>>>(ei, out);
    }
}

// round 10
// speedup vs baseline: 1.0017x; 1.0017x over previous
#include <cuda_runtime.h>
#include <cuda_bf16.h>

#define N_NODES 100000
#define N_EDGES 625000
#define NUM_SMS 148

// Combined per-node projection table: g_AB[n] = {a0+bias0, a1+bias1, b0, b1}
__device__ float4 g_AB[N_NODES];

// Self-resetting grid barrier state (zero at module load; reset each run).
__device__ unsigned int g_arrive = 0;
__device__ unsigned int g_depart = 0;

// Fused persistent kernel:
//  Phase 1: node projection (8 lanes/node-pair group, 2 nodes/group, grid-stride).
//  Grid barrier (release/acquire, self-resetting).
//  Phase 2: edge scoring, grid-stride, 2 edges/thread.
__global__ __launch_bounds__(256) void fused_kernel(
    const float4* __restrict__ x,    // [N_NODES * 32] float4
    const float4* __restrict__ W,    // [2 * 64] float4
    const float*  __restrict__ bias, // [2]
    const int2*   __restrict__ src2, // ei[0:E] as int2
    const int2*   __restrict__ dst2, // ei[E:2E] as int2
    float4*       __restrict__ out4) // 2 edges per float4
{
    const unsigned int nblocks = gridDim.x;

    // ---------------- Phase 1: node projection ----------------
    {
        int lane = threadIdx.x & 31;
        int g = lane >> 3;        // group 0..3
        int w = lane & 7;         // lane-in-group 0..7
        int warp_global = blockIdx.x * 8 + (threadIdx.x >> 5);
        const int n_warps = nblocks * 8;
        const int N_GROUPS = N_NODES / 8;   // 12500 exactly

        float bi0 = __ldg(&bias[0]);
        float bi1 = __ldg(&bias[1]);

        for (int grp = warp_global; grp < N_GROUPS; grp += n_warps) {
            int nodeA = grp * 8 + g;
            int nodeB = nodeA + 4;

            const float4* xa = x + nodeA * 32;
            const float4* xb = x + nodeB * 32;
            float4 u0 = xa[w];
            float4 u1 = xa[w + 8];
            float4 u2 = xa[w + 16];
            float4 u3 = xa[w + 24];
            float4 v0 = xb[w];
            float4 v1 = xb[w + 8];
            float4 v2 = xb[w + 16];
            float4 v3 = xb[w + 24];

            float ua0 = 0.f, ua1 = 0.f, ub0 = 0.f, ub1 = 0.f;
            float va0 = 0.f, va1 = 0.f, vb0 = 0.f, vb1 = 0.f;

            #pragma unroll
            for (int j = 0; j < 4; j++) {
                float4 u = (j == 0) ? u0 : (j == 1) ? u1 : (j == 2) ? u2 : u3;
                float4 v = (j == 0) ? v0 : (j == 1) ? v1 : (j == 2) ? v2 : v3;
                int col = w + 8 * j;
                float4 wa0 = __ldg(&W[col]);
                float4 wb0 = __ldg(&W[32 + col]);
                float4 wa1 = __ldg(&W[64 + col]);
                float4 wb1 = __ldg(&W[96 + col]);

                ua0 += u.x * wa0.x + u.y * wa0.y + u.z * wa0.z + u.w * wa0.w;
                ub0 += u.x * wb0.x + u.y * wb0.y + u.z * wb0.z + u.w * wb0.w;
                ua1 += u.x * wa1.x + u.y * wa1.y + u.z * wa1.z + u.w * wa1.w;
                ub1 += u.x * wb1.x + u.y * wb1.y + u.z * wb1.z + u.w * wb1.w;

                va0 += v.x * wa0.x + v.y * wa0.y + v.z * wa0.z + v.w * wa0.w;
                vb0 += v.x * wb0.x + v.y * wb0.y + v.z * wb0.z + v.w * wb0.w;
                va1 += v.x * wa1.x + v.y * wa1.y + v.z * wa1.z + v.w * wa1.w;
                vb1 += v.x * wb1.x + v.y * wb1.y + v.z * wb1.z + v.w * wb1.w;
            }

            #pragma unroll
            for (int off = 4; off > 0; off >>= 1) {
                ua0 += __shfl_down_sync(0xFFFFFFFFu, ua0, off);
                ua1 += __shfl_down_sync(0xFFFFFFFFu, ua1, off);
                ub0 += __shfl_down_sync(0xFFFFFFFFu, ub0, off);
                ub1 += __shfl_down_sync(0xFFFFFFFFu, ub1, off);
                va0 += __shfl_down_sync(0xFFFFFFFFu, va0, off);
                va1 += __shfl_down_sync(0xFFFFFFFFu, va1, off);
                vb0 += __shfl_down_sync(0xFFFFFFFFu, vb0, off);
                vb1 += __shfl_down_sync(0xFFFFFFFFu, vb1, off);
            }

            if (w == 0) {
                g_AB[nodeA] = make_float4(ua0 + bi0, ua1 + bi1, ub0, ub1);
                g_AB[nodeB] = make_float4(va0 + bi0, va1 + bi1, vb0, vb1);
            }
        }
    }

    // ---------------- Grid barrier (release/acquire) ----------------
    __syncthreads();
    if (threadIdx.x == 0) {
        __threadfence();                       // release g_AB stores
        atomicAdd(&g_arrive, 1u);
        while (atomicAdd(&g_arrive, 0u) < nblocks) {
            __nanosleep(64);
        }
        __threadfence();                       // acquire
    }
    __syncthreads();

    // ---------------- Phase 2: edge scoring ----------------
    {
        const int total_threads = nblocks * 256;
        const float2* AB = (const float2*)g_AB;   // A at 2*n, B at 2*n+1
        for (int t = blockIdx.x * 256 + threadIdx.x; t < N_EDGES / 2; t += total_threads) {
            int2 s = __ldg(&src2[t]);
            int2 d = __ldg(&dst2[t]);
            float2 A0 = AB[2 * s.x],     A1 = AB[2 * s.y];
            float2 B0 = AB[2 * d.x + 1], B1 = AB[2 * d.y + 1];
            out4[t] = make_float4(A0.x + B0.x, A0.y + B0.y, A1.x + B1.x, A1.y + B1.y);
        }
    }

    // ---------------- Barrier reset for next replay ----------------
    __syncthreads();
    if (threadIdx.x == 0) {
        unsigned int r = atomicAdd(&g_depart, 1u);
        if (r == nblocks - 1u) {   // last block out resets state
            g_arrive = 0u;
            g_depart = 0u;
            __threadfence();
        }
    }
}

extern "C" void kernel_launch(void* const* d_in, const int* in_sizes, int n_in,
                              void* d_out, int out_size)
{
    const float4* x    = (const float4*)d_in[0];   // [100000, 128] f32
    const int*    ei   = (const int*)d_in[1];      // [2, 625000] i32
    const float4* W    = (const float4*)d_in[2];   // [2, 256] f32
    const float*  b    = (const float*)d_in[3];    // [2] f32
    const int2*   src2 = (const int2*)ei;
    const int2*   dst2 = (const int2*)(ei + N_EDGES);
    float4*       out4 = (float4*)d_out;

    // Co-residency-safe persistent grid: query actual max blocks/SM (pure
    // query, capture-safe). Barrier target is gridDim.x inside the kernel.
    static int blocks_per_sm = 0;   // computed once; deterministic thereafter
    if (blocks_per_sm == 0) {
        int maxb = 0;
        cudaOccupancyMaxActiveBlocksPerMultiprocessor(&maxb, fused_kernel, 256, 0);
        if (maxb < 1) maxb = 1;
        if (maxb > 6) maxb = 6;     // no benefit beyond this; keep dispatch tight
        blocks_per_sm = maxb;
    }
    unsigned int grid = (unsigned int)(blocks_per_sm * NUM_SMS);

    fused_kernel<<<grid, 256>>>(x, W, b, src2, dst2, out4);
}